// round 17
// baseline (speedup 1.0000x reference)
#include <cuda_runtime.h>
#include <cstdint>

#define WARM_UP 365
#define NPHY    12
#define NMUL    4
#define LENF    15
#define MAX_T   2000
#define MAX_G   4000
#define CHUNK   40
#define GPB     32                 // grid cells per block
#define THREADS (GPB * NMUL)       // 128, thread = (g, m)
#define QROWS   (CHUNK + LENF - 1) // 54: 14 history rows + 40 chunk rows
#define HROWS   (LENF - 1)         // 14

// dynamic smem layout (floats)
#define SBUF_FLOATS ((CHUNK + 1) * GPB * 3)          // 3936 each
#define OFF_SBUFA   0
#define OFF_SBUFB   (SBUF_FLOATS)
#define OFF_QSM     (2 * SBUF_FLOATS)                // CHUNK*THREADS = 5120
#define OFF_QAVG    (OFF_QSM + CHUNK * THREADS)      // QROWS*GPB = 1728
#define OFF_HIST0   (OFF_QAVG + QROWS * GPB)         // 448
#define OFF_HIST1   (OFF_HIST0 + HROWS * GPB)        // 448
#define OFF_WSM     (OFF_HIST1 + HROWS * GPB)        // LENF*GPB = 480
#define SMEM_FLOATS (OFF_WSM + LENF * GPB)
#define SMEM_BYTES  (SMEM_FLOATS * 4)

__device__ __forceinline__ float fast_lg2(float x) {
    float r; asm("lg2.approx.f32 %0, %1;" : "=f"(r) : "f"(x)); return r;
}
__device__ __forceinline__ float fast_ex2(float x) {
    float r; asm("ex2.approx.f32 %0, %1;" : "=f"(r) : "f"(x)); return r;
}
__device__ __forceinline__ uint32_t smem_u32(const void* p) {
    return (uint32_t)__cvta_generic_to_shared(p);
}

// ---------------------------------------------------------------------------
// Fully fused HBV: scan + m-average + gamma routing weights + 15-tap conv.
// Thread = (g, m) for the scan; per chunk, pass1 averages q into qavg (smem)
// and builds next-chunk history; pass2 convolves and stores directly to out.
// EXACT=true: G % GPB == 0 and T % CHUNK == 0 -> no per-iteration branches.
// ---------------------------------------------------------------------------
template <bool EXACT>
__global__ __launch_bounds__(THREADS)
void hbv_fused_kernel(const float* __restrict__ x_phy,
                      const float* __restrict__ params,
                      float* __restrict__ out,
                      int T, int G)
{
    extern __shared__ float dynsm[];
    float (*sbufA)[GPB * 3] = (float (*)[GPB * 3])(dynsm + OFF_SBUFA);
    float (*sbufB)[GPB * 3] = (float (*)[GPB * 3])(dynsm + OFF_SBUFB);
    float (*qsm)[THREADS]   = (float (*)[THREADS])(dynsm + OFF_QSM);
    float* qavg  = dynsm + OFF_QAVG;    // [QROWS][GPB] flat
    float* hist0 = dynsm + OFF_HIST0;   // [HROWS][GPB] flat
    float* hist1 = dynsm + OFF_HIST1;
    float* wsm   = dynsm + OFF_WSM;     // [LENF][GPB] flat

    const int tidx = threadIdx.x;
    const int gl   = tidx >> 2;
    const int m    = tidx & 3;
    const int g0   = blockIdx.x * GPB;
    const int g    = g0 + gl;
    const bool active = EXACT || (g < G);

    const float lb[NPHY] = {1.0f, 50.0f, 0.05f, 0.01f, 0.001f, 0.2f,
                            0.0f, 0.0f, -2.5f, 0.5f, 0.0f, 0.0f};
    const float ub[NPHY] = {6.0f, 1000.0f, 0.9f, 0.5f, 0.2f, 1.0f,
                            10.0f, 100.0f, 2.5f, 10.0f, 0.1f, 0.2f};

    float phy[NPHY];
#pragma unroll
    for (int i = 0; i < NPHY; i++) phy[i] = 0.5f;
    if (active) {
        const float* pp = params + (size_t)g * (NPHY * NMUL + 2);
#pragma unroll
        for (int i = 0; i < NPHY; i++)
            phy[i] = lb[i] + pp[i * NMUL + m] * (ub[i] - lb[i]);
    }
    const float beta  = phy[0],  fc    = phy[1],  k0  = phy[2];
    const float k1    = phy[3],  k2    = phy[4],  lp  = phy[5];
    const float perc  = phy[6],  uzl   = phy[7],  tt  = phy[8];
    const float cfmax = phy[9],  cfr   = phy[10], cwh = phy[11];

    const float inv_lpfc  = 1.0f / (lp * fc);
    const float cfr_cfmax = cfr * cfmax;
    const float blg_ifc   = beta * fast_lg2(1.0f / fc);
    const float onek0     = 1.0f - k0;
    const float k0uzl     = k0 * uzl;
    const float c1        = 1.0f - k1;
    const float c2        = 1.0f - k2;

    float snowpack = 0.001f, meltwater = 0.001f, sm = 0.001f;
    float suz = 0.001f, slz = 0.001f;

    const int row = G * 3;
    const float* gsrc = x_phy + (size_t)blockIdx.x * (GPB * 3);
    const int fbase = gl * 3;

    auto issue_chunk = [&](float (*sb)[GPB * 3], int t0) {
        const int PK = GPB * 3 / 4;
        const int NV4 = CHUNK * PK;
#pragma unroll 2
        for (int idx = tidx; idx < NV4; idx += THREADS) {
            int i = idx / PK;
            int j = idx - i * PK;
            int t = t0 + i;
            if (!EXACT && t >= T) t = T - 1;
            const float* src = gsrc + (size_t)t * row + j * 4;
            uint32_t dst = smem_u32(&sb[i][j * 4]);
            asm volatile("cp.async.cg.shared.global [%0], [%1], 16;"
                         :: "r"(dst), "l"(src));
        }
        asm volatile("cp.async.commit_group;");
    };

    issue_chunk(sbufA, 0);

    // ---- gamma routing weights (overlaps first cp.async) ----
    // Normalizer Γ(aa)·th^aa cancels under w / w.sum().
    if (tidx < GPB && (EXACT || g0 + tidx < G)) {
        const float* pp = params + (size_t)(g0 + tidx) * (NPHY * NMUL + 2);
        float a  = pp[NPHY * NMUL + 0] * 2.9f;
        float b  = pp[NPHY * NMUL + 1] * 6.5f;
        float aa = fmaxf(a, 0.0f) + 0.1f;
        float th = fmaxf(b, 0.0f) + 0.5f;
        float inv_th = 1.0f / th;
        float wv[LENF], s = 0.0f;
#pragma unroll
        for (int k = 0; k < LENF; k++) {
            float tg = (float)k + 0.5f;
            float v = expf((aa - 1.0f) * logf(tg) - tg * inv_th);
            wv[k] = v; s += v;
        }
        float inv_s = 1.0f / s;
#pragma unroll
        for (int k = 0; k < LENF; k++)
            wsm[k * GPB + tidx] = wv[k] * inv_s;
    }

    asm volatile("cp.async.wait_group 0;");
    __syncthreads();     // sbufA + wsm ready

    // pass2 role: thread -> (gp2, 10 consecutive chunk steps)
    const int gp2    = tidx & 31;
    const int istart = (tidx >> 5) * (CHUNK / 4);
    float wr[LENF];
#pragma unroll
    for (int k = 0; k < LENF; k++)
        wr[k] = wsm[k * GPB + gp2];

    // pipelined forcing-derived terms (all off-chain)
    float rain, snow, melt_cap, refr_cap, PE, om_pe;
    auto make_terms = [&](const float* f) {
        float P  = f[0];
        float Tt = f[1];
        PE       = f[2];
        float d  = Tt - tt;
        rain = (d >= 0.0f) ? P : 0.0f;
        snow = P - rain;
        melt_cap = fmaxf(cfmax * d, 0.0f);
        refr_cap = fmaxf(-cfr_cfmax * d, 0.0f);
        om_pe = 1.0f - PE * inv_lpfc;
    };
    make_terms(&sbufA[0][fbase]);

    const int nchunks = (T + CHUNK - 1) / CHUNK;
    float (*cur)[GPB * 3] = sbufA;
    float (*nxt)[GPB * 3] = sbufB;
    float* histPrev = hist0;
    float* histNext = hist1;

    for (int c = 0; c < nchunks; c++) {
        const int t0 = c * CHUNK;
        const bool has_next = (c + 1 < nchunks);
        if (has_next)
            issue_chunk(nxt, t0 + CHUNK);

        // ================= scan: 40 steps =================
#pragma unroll 8
        for (int i = 0; i < CHUNK; i++) {
            // soil wetness: sm <= fc invariant => sw <= 1, no clamp
            float sw = fast_ex2(fmaf(beta, fast_lg2(sm), blg_ifc));

            // snow module: melt/refreeze merged (one of the caps is 0)
            float sp1 = snowpack + snow;
            float a   = fminf(melt_cap, sp1);
            float b   = fminf(refr_cap, meltwater);
            float transfer = a - b;
            float sp3 = sp1 - transfer;
            float mw2 = meltwater + transfer;
            float thr = cwh * sp3;
            float tosoil = fmaxf(mw2 - thr, 0.0f);
            meltwater = fminf(mw2, thr);
            snowpack  = sp3;

            // soil module
            float inflow   = rain + tosoil;
            float sminf    = sm + inflow;
            float recharge = inflow * sw;
            float sm2 = sminf - recharge;
            float sm3 = fminf(sm2, fc);
            float excess = sm2 - sm3;
            sm = fmaxf(fmaxf(sm3 * om_pe, sm3 - PE), 1e-5f);

            // response routing (q assembled off-chain)
            float suz1 = suz + recharge + excess;
            float suz2 = fmaxf(suz1 - perc, 0.0f);
            float suz3 = fminf(suz2, fmaf(onek0, suz2, k0uzl));
            float suzn = c1 * suz3;
            float prc  = suz1 - suz2;
            float slz1 = slz + prc;
            float q2   = k2 * slz1;
            float q01  = suz2 - suzn;
            suz = suzn;
            slz = c2 * slz1;

            make_terms(&cur[i + 1][fbase]);
            qsm[i][tidx] = q01 + q2;
        }

        __syncthreads();     // qsm complete
        // ================= pass1: average + history =================
        // (a) previous chunk's tail -> qavg history rows 0..13
#pragma unroll
        for (int k = 0; k < (HROWS * GPB + THREADS - 1) / THREADS; k++) {
            int idx = tidx + k * THREADS;
            if (idx < HROWS * GPB)
                qavg[idx] = histPrev[idx];
        }
        // (b) average this chunk's q into qavg rows 14..53
#pragma unroll
        for (int k = 0; k < (CHUNK * GPB) / THREADS; k++) {
            int idx = tidx + k * THREADS;
            int ii  = idx >> 5;
            int gp  = idx & 31;
            float4 v = *(const float4*)&qsm[ii][gp << 2];
            qavg[(HROWS + ii) * GPB + gp] = 0.25f * ((v.x + v.y) + (v.z + v.w));
        }
        // (c) this chunk's tail (steps 26..39) -> histNext
#pragma unroll
        for (int k = 0; k < (HROWS * GPB + THREADS - 1) / THREADS; k++) {
            int idx = tidx + k * THREADS;
            if (idx < HROWS * GPB) {
                int r  = idx >> 5;
                int gp = idx & 31;
                float4 v = *(const float4*)&qsm[(CHUNK - HROWS + r)][gp << 2];
                histNext[idx] = 0.25f * ((v.x + v.y) + (v.z + v.w));
            }
        }
        __syncthreads();     // qavg ready

        // ================= pass2: conv + store =================
        if (t0 + CHUNK > WARM_UP) {
            float qb[HROWS];     // q[t-14 .. t-1] rolling window
#pragma unroll
            for (int j = 0; j < HROWS; j++)
                qb[j] = qavg[(istart + j) * GPB + gp2];
#pragma unroll
            for (int u = 0; u < CHUNK / 4; u++) {
                int ii = istart + u;
                float qt = qavg[(HROWS + ii) * GPB + gp2];
                float acc = qt * wr[0];
#pragma unroll
                for (int k = 1; k < LENF; k++)
                    acc += qb[LENF - 1 - k] * wr[k];
                int t = t0 + ii;
                bool w_ok = (t >= WARM_UP) && (EXACT || t < T)
                            && (EXACT || (g0 + gp2) < G);
                if (w_ok)
                    out[(size_t)(t - WARM_UP) * G + g0 + gp2] = acc;
#pragma unroll
                for (int j = 0; j < HROWS - 1; j++)
                    qb[j] = qb[j + 1];
                qb[HROWS - 1] = qt;
            }
        }

        // swap history buffers
        { float* th = histPrev; histPrev = histNext; histNext = th; }

        if (has_next) {
            asm volatile("cp.async.wait_group 0;");
            __syncthreads();     // copies landed; qavg/qsm consumers done
            float (*tmp)[GPB * 3] = cur; cur = nxt; nxt = tmp;
            make_terms(&cur[0][fbase]);
        }
    }
}

// ---------------------------------------------------------------------------
extern "C" void kernel_launch(void* const* d_in, const int* in_sizes, int n_in,
                              void* d_out, int out_size)
{
    int ix = 0, ip = 1;
    if (in_sizes[0] < in_sizes[1]) { ix = 1; ip = 0; }
    const float* x_phy  = (const float*)d_in[ix];
    const float* params = (const float*)d_in[ip];
    float* out = (float*)d_out;

    int G = in_sizes[ip] / (NPHY * NMUL + 2);
    int T = in_sizes[ix] / (3 * G);

    // idempotent attribute set (not an allocation; capture-safe host call)
    cudaFuncSetAttribute(hbv_fused_kernel<true>,
                         cudaFuncAttributeMaxDynamicSharedMemorySize, SMEM_BYTES);
    cudaFuncSetAttribute(hbv_fused_kernel<false>,
                         cudaFuncAttributeMaxDynamicSharedMemorySize, SMEM_BYTES);

    int nblk = (G + GPB - 1) / GPB;
    if ((G % GPB) == 0 && (T % CHUNK) == 0)
        hbv_fused_kernel<true><<<nblk, THREADS, SMEM_BYTES>>>(x_phy, params, out, T, G);
    else
        hbv_fused_kernel<false><<<nblk, THREADS, SMEM_BYTES>>>(x_phy, params, out, T, G);
}